// round 2
// baseline (speedup 1.0000x reference)
#include <cuda_runtime.h>

#define T_TOK 4096
#define H_DIM 1024
#define F_DIM 2816
#define N_EXP 8
#define BM 128
#define BN 64
#define BK 16
#define MAX_TILES 32          // ceil(4096 / 128)
#define CAP 9216              // 8192 pairs + 8*128 padding

// ---------------- scratch (device globals; no allocation allowed) ----------
__device__ float g_x  [(size_t)T_TOK * H_DIM];    // rmsnormed x
__device__ float g_xg [(size_t)CAP   * H_DIM];    // gathered (expert-grouped) x rows
__device__ float g_h  [(size_t)CAP   * F_DIM];    // combine * silu(gate) * up
__device__ float g_part[2][(size_t)T_TOK * H_DIM];// per-topk-slot partial outputs
__device__ int   g_cnt [N_EXP];
__device__ int   g_fill[N_EXP];
__device__ int   g_seg [N_EXP + 1];
__device__ int   g_ptok[CAP];
__device__ float g_pscale[CAP];
__device__ int   g_pslot[CAP];
__device__ int   g_topi[T_TOK * 2];
__device__ float g_topp[T_TOK * 2];

// ---------------- 0: reset counters, mark all pair slots invalid ----------
__global__ void k_init() {
    int i = blockIdx.x * blockDim.x + threadIdx.x;
    if (i < N_EXP) { g_cnt[i] = 0; g_fill[i] = 0; }
    if (i < CAP) g_ptok[i] = -1;
}

// ---------------- 1: RMSNorm ----------------------------------------------
__global__ void k_rmsnorm(const float* __restrict__ hs, const float* __restrict__ lnw) {
    int t = blockIdx.x;
    const float4* row = (const float4*)(hs + (size_t)t * H_DIM);
    __shared__ float red[256];
    float4 v = row[threadIdx.x];                 // 256 threads * float4 = 1024
    float s = v.x * v.x + v.y * v.y + v.z * v.z + v.w * v.w;
    red[threadIdx.x] = s;
    __syncthreads();
    for (int off = 128; off > 0; off >>= 1) {
        if (threadIdx.x < off) red[threadIdx.x] += red[threadIdx.x + off];
        __syncthreads();
    }
    float rs = rsqrtf(red[0] * (1.0f / H_DIM) + 1e-5f);
    float4 w = ((const float4*)lnw)[threadIdx.x];
    float4 o;
    o.x = v.x * rs * w.x; o.y = v.y * rs * w.y;
    o.z = v.z * rs * w.z; o.w = v.w * rs * w.w;
    ((float4*)(g_x + (size_t)t * H_DIM))[threadIdx.x] = o;
}

// ---------------- 2: router: logits -> softmax -> top2 + counts ----------
__global__ void k_router(const float* __restrict__ rw) {
    int t = blockIdx.x * blockDim.x + threadIdx.x;
    if (t >= T_TOK) return;
    const float* xr = g_x + (size_t)t * H_DIM;
    float acc[8] = {0, 0, 0, 0, 0, 0, 0, 0};
    for (int k = 0; k < H_DIM; k++) {
        float xv = __ldg(xr + k);
        float4 r0 = ((const float4*)rw)[k * 2];
        float4 r1 = ((const float4*)rw)[k * 2 + 1];
        acc[0] += xv * r0.x; acc[1] += xv * r0.y;
        acc[2] += xv * r0.z; acc[3] += xv * r0.w;
        acc[4] += xv * r1.x; acc[5] += xv * r1.y;
        acc[6] += xv * r1.z; acc[7] += xv * r1.w;
    }
    float m = acc[0];
    #pragma unroll
    for (int e = 1; e < 8; e++) m = fmaxf(m, acc[e]);
    float p[8]; float s = 0.f;
    #pragma unroll
    for (int e = 0; e < 8; e++) { p[e] = expf(acc[e] - m); s += p[e]; }
    float inv = 1.f / s;
    int i0 = 0; float b0 = p[0];
    #pragma unroll
    for (int e = 1; e < 8; e++) if (p[e] > b0) { b0 = p[e]; i0 = e; }
    int i1 = -1; float b1 = -1.f;
    #pragma unroll
    for (int e = 0; e < 8; e++) if (e != i0 && p[e] > b1) { b1 = p[e]; i1 = e; }
    g_topi[t * 2] = i0;       g_topi[t * 2 + 1] = i1;
    g_topp[t * 2] = b0 * inv; g_topp[t * 2 + 1] = b1 * inv;
    atomicAdd(&g_cnt[i0], 1);
    atomicAdd(&g_cnt[i1], 1);
}

// ---------------- 3: padded segment offsets (single thread, tiny) --------
__global__ void k_offsets() {
    if (threadIdx.x == 0 && blockIdx.x == 0) {
        int off = 0;
        for (int e = 0; e < N_EXP; e++) {
            g_seg[e] = off;
            off += ((g_cnt[e] + BM - 1) / BM) * BM;
        }
        g_seg[N_EXP] = off;
    }
}

// ---------------- 4: scatter (token,slot) pairs into expert segments -----
__global__ void k_scatter() {
    int t = blockIdx.x * blockDim.x + threadIdx.x;
    if (t >= T_TOK) return;
    #pragma unroll
    for (int k = 0; k < 2; k++) {
        int e = g_topi[t * 2 + k];
        int pos = atomicAdd(&g_fill[e], 1);
        int idx = g_seg[e] + pos;
        g_ptok[idx] = t;
        g_pscale[idx] = g_topp[t * 2 + k];
        g_pslot[idx] = k;
    }
}

// ---------------- 5: gather x rows into contiguous expert-grouped buffer --
__global__ void k_gather() {
    int p = blockIdx.x;                       // CAP blocks
    int tok = g_ptok[p];
    float4* dst = (float4*)(g_xg + (size_t)p * H_DIM);
    if (tok >= 0) {
        const float4* src = (const float4*)(g_x + (size_t)tok * H_DIM);
        dst[threadIdx.x] = src[threadIdx.x];
    } else {
        dst[threadIdx.x] = make_float4(0.f, 0.f, 0.f, 0.f);
    }
}

// ---------------- 6: fused gate+up GEMM with SiLU*combine epilogue --------
__global__ __launch_bounds__(256)
void k_gemm1(const float* __restrict__ wg, const float* __restrict__ wu) {
    int e = blockIdx.x / MAX_TILES;
    int tile = blockIdx.x % MAX_TILES;
    int row0 = tile * BM;
    if (row0 >= g_cnt[e]) return;
    int seg = g_seg[e];
    int nblk = blockIdx.y * BN;

    __shared__ float As[BK][BM + 4];
    __shared__ float Bs[2][BK][BN + 4];
    __shared__ float sScale[BM];

    int tid = threadIdx.x;
    if (tid < BM) sScale[tid] = g_pscale[seg + row0 + tid];

    const float* abase = g_xg + (size_t)(seg + row0) * H_DIM;
    const float* gb = wg + (size_t)e * H_DIM * F_DIM + nblk;
    const float* ub = wu + (size_t)e * H_DIM * F_DIM + nblk;

    int am0 = tid >> 2, aks = tid & 3;   // A: 64 rows x 4 float4-segs (x2 reps)
    int btk = tid >> 4, btn = tid & 15;  // B: 16 k-rows x 16 float4
    int ty = tid >> 4, tx = tid & 15;

    float accg[8][4], accu[8][4];
    #pragma unroll
    for (int i = 0; i < 8; i++)
        #pragma unroll
        for (int j = 0; j < 4; j++) { accg[i][j] = 0.f; accu[i][j] = 0.f; }

    for (int kk = 0; kk < H_DIM; kk += BK) {
        float4 a0 = *(const float4*)(abase + (size_t)am0 * H_DIM + kk + aks * 4);
        float4 a1 = *(const float4*)(abase + (size_t)(am0 + 64) * H_DIM + kk + aks * 4);
        float4 bg = *(const float4*)(gb + (size_t)(kk + btk) * F_DIM + btn * 4);
        float4 bu = *(const float4*)(ub + (size_t)(kk + btk) * F_DIM + btn * 4);
        __syncthreads();
        As[aks * 4 + 0][am0] = a0.x; As[aks * 4 + 1][am0] = a0.y;
        As[aks * 4 + 2][am0] = a0.z; As[aks * 4 + 3][am0] = a0.w;
        As[aks * 4 + 0][am0 + 64] = a1.x; As[aks * 4 + 1][am0 + 64] = a1.y;
        As[aks * 4 + 2][am0 + 64] = a1.z; As[aks * 4 + 3][am0 + 64] = a1.w;
        *(float4*)&Bs[0][btk][btn * 4] = bg;
        *(float4*)&Bs[1][btk][btn * 4] = bu;
        __syncthreads();
        #pragma unroll
        for (int k = 0; k < BK; k++) {
            float4 af0 = *(const float4*)&As[k][ty * 8];
            float4 af1 = *(const float4*)&As[k][ty * 8 + 4];
            float4 bgf = *(const float4*)&Bs[0][k][tx * 4];
            float4 buf4 = *(const float4*)&Bs[1][k][tx * 4];
            float a[8] = {af0.x, af0.y, af0.z, af0.w, af1.x, af1.y, af1.z, af1.w};
            float bgv[4] = {bgf.x, bgf.y, bgf.z, bgf.w};
            float buv[4] = {buf4.x, buf4.y, buf4.z, buf4.w};
            #pragma unroll
            for (int i = 0; i < 8; i++)
                #pragma unroll
                for (int j = 0; j < 4; j++) {
                    accg[i][j] += a[i] * bgv[j];
                    accu[i][j] += a[i] * buv[j];
                }
        }
    }

    float* hb = g_h + (size_t)(seg + row0) * F_DIM + nblk;
    #pragma unroll
    for (int i = 0; i < 8; i++) {
        int m = ty * 8 + i;
        float sc = sScale[m];
        float4 o;
        float g0 = accg[i][0], g1 = accg[i][1], g2 = accg[i][2], g3 = accg[i][3];
        o.x = sc * (g0 / (1.f + __expf(-g0))) * accu[i][0];
        o.y = sc * (g1 / (1.f + __expf(-g1))) * accu[i][1];
        o.z = sc * (g2 / (1.f + __expf(-g2))) * accu[i][2];
        o.w = sc * (g3 / (1.f + __expf(-g3))) * accu[i][3];
        *(float4*)(hb + (size_t)m * F_DIM + tx * 4) = o;
    }
}

// ---------------- 7: down GEMM -> per-slot partial outputs ----------------
__global__ __launch_bounds__(256)
void k_gemm2(const float* __restrict__ wd) {
    int e = blockIdx.x / MAX_TILES;
    int tile = blockIdx.x % MAX_TILES;
    int row0 = tile * BM;
    if (row0 >= g_cnt[e]) return;
    int seg = g_seg[e];
    int nblk = blockIdx.y * BN;

    __shared__ float As[BK][BM + 4];
    __shared__ float Bsd[BK][BN + 4];
    __shared__ int sTok[BM];
    __shared__ int sSlot[BM];

    int tid = threadIdx.x;
    if (tid < BM) {
        sTok[tid] = g_ptok[seg + row0 + tid];
        sSlot[tid] = g_pslot[seg + row0 + tid];
    }

    const float* abase = g_h + (size_t)(seg + row0) * F_DIM;
    const float* db = wd + (size_t)e * F_DIM * H_DIM + nblk;

    int am0 = tid >> 2, aks = tid & 3;
    int btk = tid >> 4, btn = tid & 15;
    int ty = tid >> 4, tx = tid & 15;

    float acc[8][4];
    #pragma unroll
    for (int i = 0; i < 8; i++)
        #pragma unroll
        for (int j = 0; j < 4; j++) acc[i][j] = 0.f;

    for (int kk = 0; kk < F_DIM; kk += BK) {
        float4 a0 = *(const float4*)(abase + (size_t)am0 * F_DIM + kk + aks * 4);
        float4 a1 = *(const float4*)(abase + (size_t)(am0 + 64) * F_DIM + kk + aks * 4);
        float4 b = *(const float4*)(db + (size_t)(kk + btk) * H_DIM + btn * 4);
        __syncthreads();
        As[aks * 4 + 0][am0] = a0.x; As[aks * 4 + 1][am0] = a0.y;
        As[aks * 4 + 2][am0] = a0.z; As[aks * 4 + 3][am0] = a0.w;
        As[aks * 4 + 0][am0 + 64] = a1.x; As[aks * 4 + 1][am0 + 64] = a1.y;
        As[aks * 4 + 2][am0 + 64] = a1.z; As[aks * 4 + 3][am0 + 64] = a1.w;
        *(float4*)&Bsd[btk][btn * 4] = b;
        __syncthreads();
        #pragma unroll
        for (int k = 0; k < BK; k++) {
            float4 af0 = *(const float4*)&As[k][ty * 8];
            float4 af1 = *(const float4*)&As[k][ty * 8 + 4];
            float4 bf = *(const float4*)&Bsd[k][tx * 4];
            float a[8] = {af0.x, af0.y, af0.z, af0.w, af1.x, af1.y, af1.z, af1.w};
            float bv[4] = {bf.x, bf.y, bf.z, bf.w};
            #pragma unroll
            for (int i = 0; i < 8; i++)
                #pragma unroll
                for (int j = 0; j < 4; j++) acc[i][j] += a[i] * bv[j];
        }
    }

    #pragma unroll
    for (int i = 0; i < 8; i++) {
        int m = ty * 8 + i;
        int tok = sTok[m];
        if (tok >= 0) {
            int slot = sSlot[m];
            float4 o = make_float4(acc[i][0], acc[i][1], acc[i][2], acc[i][3]);
            *(float4*)&g_part[slot][(size_t)tok * H_DIM + nblk + tx * 4] = o;
        }
    }
}

// ---------------- 8: sum slot partials ------------------------------------
__global__ void k_final(float* __restrict__ out) {
    int i = blockIdx.x * blockDim.x + threadIdx.x;   // float4 index
    float4 a = ((const float4*)g_part[0])[i];
    float4 b = ((const float4*)g_part[1])[i];
    float4 o;
    o.x = a.x + b.x; o.y = a.y + b.y; o.z = a.z + b.z; o.w = a.w + b.w;
    ((float4*)out)[i] = o;
}

// ---------------- launcher -------------------------------------------------
extern "C" void kernel_launch(void* const* d_in, const int* in_sizes, int n_in,
                              void* d_out, int out_size) {
    const float* hs  = (const float*)d_in[0];
    const float* lnw = (const float*)d_in[1];
    const float* rw  = (const float*)d_in[2];
    const float* wg  = (const float*)d_in[3];
    const float* wu  = (const float*)d_in[4];
    const float* wd  = (const float*)d_in[5];
    float* out = (float*)d_out;

    k_init<<<(CAP + 255) / 256, 256>>>();
    k_rmsnorm<<<T_TOK, 256>>>(hs, lnw);
    k_router<<<T_TOK / 256, 256>>>(rw);
    k_offsets<<<1, 32>>>();
    k_scatter<<<T_TOK / 256, 256>>>();
    k_gather<<<CAP, 256>>>();
    k_gemm1<<<dim3(N_EXP * MAX_TILES, F_DIM / BN), 256>>>(wg, wu);
    k_gemm2<<<dim3(N_EXP * MAX_TILES, H_DIM / BN), 256>>>(wd);
    k_final<<<(T_TOK * H_DIM / 4) / 256, 256>>>(out);
}

// round 6
// speedup vs baseline: 1.7037x; 1.7037x over previous
#include <cuda_runtime.h>
#include <cuda_bf16.h>
#include <cstdint>

#define T_TOK 4096
#define H_DIM 1024
#define F_DIM 2816
#define N_EXP 8
#define BM 128
#define MAX_TILES 32
#define CAP 9216

#define SM_PITCH 80                 // bytes per 32-bf16 smem row (20 banks -> conflict-free)
#define STAGE_ROWS 512
#define STAGE_BYTES (STAGE_ROWS * SM_PITCH)   // 40960
#define NSTAGE 3
#define GEMM_SMEM (NSTAGE * STAGE_BYTES)      // 122880

// ---------------- scratch (device globals) --------------------------------
__device__ float          g_x[(size_t)T_TOK * H_DIM];
__device__ __nv_bfloat16  g_xg_hi[(size_t)CAP * H_DIM];
__device__ __nv_bfloat16  g_xg_lo[(size_t)CAP * H_DIM];
__device__ __nv_bfloat16  g_h_hi[(size_t)CAP * F_DIM];
__device__ __nv_bfloat16  g_h_lo[(size_t)CAP * F_DIM];
__device__ __nv_bfloat16  g_wgt_hi[(size_t)N_EXP * F_DIM * H_DIM];  // [e][f][h]
__device__ __nv_bfloat16  g_wgt_lo[(size_t)N_EXP * F_DIM * H_DIM];
__device__ __nv_bfloat16  g_wut_hi[(size_t)N_EXP * F_DIM * H_DIM];
__device__ __nv_bfloat16  g_wut_lo[(size_t)N_EXP * F_DIM * H_DIM];
__device__ __nv_bfloat16  g_wdt_hi[(size_t)N_EXP * H_DIM * F_DIM];  // [e][h][f]
__device__ __nv_bfloat16  g_wdt_lo[(size_t)N_EXP * H_DIM * F_DIM];
__device__ float          g_part[2][(size_t)T_TOK * H_DIM];
__device__ int   g_cnt[N_EXP];
__device__ int   g_fill[N_EXP];
__device__ int   g_seg[N_EXP + 1];
__device__ int   g_ptok[CAP];
__device__ float g_pscale[CAP];
__device__ int   g_pslot[CAP];
__device__ int   g_topi[T_TOK * 2];
__device__ float g_topp[T_TOK * 2];

// ---------------- helpers --------------------------------------------------
__device__ __forceinline__ uint32_t smem_u32(const void* p) {
    uint32_t a;
    asm("{ .reg .u64 t; cvta.to.shared.u64 t, %1; cvt.u32.u64 %0, t; }" : "=r"(a) : "l"(p));
    return a;
}
__device__ __forceinline__ void cp16(uint32_t dst, const void* src) {
    asm volatile("cp.async.cg.shared.global [%0], [%1], 16;" :: "r"(dst), "l"(src));
}
__device__ __forceinline__ void cp_commit() {
    asm volatile("cp.async.commit_group;" ::: "memory");
}
__device__ __forceinline__ void cp_wait2() {
    asm volatile("cp.async.wait_group 2;" ::: "memory");
}
__device__ __forceinline__ uint32_t lds32(uint32_t a) {
    uint32_t v; asm volatile("ld.shared.b32 %0, [%1];" : "=r"(v) : "r"(a)); return v;
}
__device__ __forceinline__ void mma16816(float* c, const uint32_t* a, uint32_t b0, uint32_t b1) {
    asm volatile(
        "mma.sync.aligned.m16n8k16.row.col.f32.bf16.bf16.f32 "
        "{%0,%1,%2,%3}, {%4,%5,%6,%7}, {%8,%9}, {%0,%1,%2,%3};"
        : "+f"(c[0]), "+f"(c[1]), "+f"(c[2]), "+f"(c[3])
        : "r"(a[0]), "r"(a[1]), "r"(a[2]), "r"(a[3]), "r"(b0), "r"(b1));
}
__device__ __forceinline__ uint32_t pack2(__nv_bfloat16 a, __nv_bfloat16 b) {
    return (uint32_t)__bfloat16_as_ushort(a) | ((uint32_t)__bfloat16_as_ushort(b) << 16);
}

// ---------------- 0: init --------------------------------------------------
__global__ void k_init() {
    int i = blockIdx.x * blockDim.x + threadIdx.x;
    if (i < N_EXP) { g_cnt[i] = 0; g_fill[i] = 0; }
    if (i < CAP) { g_ptok[i] = -1; g_pscale[i] = 0.f; }
}

// ---------------- 1: RMSNorm ----------------------------------------------
__global__ void k_rmsnorm(const float* __restrict__ hs, const float* __restrict__ lnw) {
    int t = blockIdx.x;
    const float4* row = (const float4*)(hs + (size_t)t * H_DIM);
    __shared__ float red[256];
    float4 v = row[threadIdx.x];
    float s = v.x * v.x + v.y * v.y + v.z * v.z + v.w * v.w;
    red[threadIdx.x] = s;
    __syncthreads();
    for (int off = 128; off > 0; off >>= 1) {
        if (threadIdx.x < off) red[threadIdx.x] += red[threadIdx.x + off];
        __syncthreads();
    }
    float rs = rsqrtf(red[0] * (1.0f / H_DIM) + 1e-5f);
    float4 w = ((const float4*)lnw)[threadIdx.x];
    float4 o;
    o.x = v.x * rs * w.x; o.y = v.y * rs * w.y;
    o.z = v.z * rs * w.z; o.w = v.w * rs * w.w;
    ((float4*)(g_x + (size_t)t * H_DIM))[threadIdx.x] = o;
}

// ---------------- 2: weight transpose + bf16 hi/lo split ------------------
__global__ void k_transpose_split(const float* __restrict__ src, int which, int R, int C) {
    __shared__ float t[32][33];
    size_t eoff = (size_t)blockIdx.z * (size_t)R * C;
    int c0 = blockIdx.x * 32, r0 = blockIdx.y * 32;
    const float* s = src + eoff;
    #pragma unroll
    for (int i = threadIdx.y; i < 32; i += 8)
        t[i][threadIdx.x] = s[(size_t)(r0 + i) * C + c0 + threadIdx.x];
    __syncthreads();
    __nv_bfloat16 *dhi, *dlo;
    if (which == 0)      { dhi = g_wgt_hi; dlo = g_wgt_lo; }
    else if (which == 1) { dhi = g_wut_hi; dlo = g_wut_lo; }
    else                 { dhi = g_wdt_hi; dlo = g_wdt_lo; }
    dhi += eoff; dlo += eoff;
    #pragma unroll
    for (int i = threadIdx.y; i < 32; i += 8) {
        int ro = c0 + i;
        int co = r0 + threadIdx.x;
        float v = t[threadIdx.x][i];
        __nv_bfloat16 h = __float2bfloat16(v);
        __nv_bfloat16 l = __float2bfloat16(v - __bfloat162float(h));
        dhi[(size_t)ro * R + co] = h;
        dlo[(size_t)ro * R + co] = l;
    }
}

// ---------------- 3: router ------------------------------------------------
__global__ void k_router(const float* __restrict__ rw) {
    int t = blockIdx.x * blockDim.x + threadIdx.x;
    if (t >= T_TOK) return;
    const float* xr = g_x + (size_t)t * H_DIM;
    float acc[8] = {0, 0, 0, 0, 0, 0, 0, 0};
    for (int k = 0; k < H_DIM; k++) {
        float xv = __ldg(xr + k);
        float4 r0 = ((const float4*)rw)[k * 2];
        float4 r1 = ((const float4*)rw)[k * 2 + 1];
        acc[0] += xv * r0.x; acc[1] += xv * r0.y;
        acc[2] += xv * r0.z; acc[3] += xv * r0.w;
        acc[4] += xv * r1.x; acc[5] += xv * r1.y;
        acc[6] += xv * r1.z; acc[7] += xv * r1.w;
    }
    float m = acc[0];
    #pragma unroll
    for (int e = 1; e < 8; e++) m = fmaxf(m, acc[e]);
    float p[8]; float s = 0.f;
    #pragma unroll
    for (int e = 0; e < 8; e++) { p[e] = expf(acc[e] - m); s += p[e]; }
    float inv = 1.f / s;
    int i0 = 0; float b0 = p[0];
    #pragma unroll
    for (int e = 1; e < 8; e++) if (p[e] > b0) { b0 = p[e]; i0 = e; }
    int i1 = -1; float b1 = -1.f;
    #pragma unroll
    for (int e = 0; e < 8; e++) if (e != i0 && p[e] > b1) { b1 = p[e]; i1 = e; }
    g_topi[t * 2] = i0;       g_topi[t * 2 + 1] = i1;
    g_topp[t * 2] = b0 * inv; g_topp[t * 2 + 1] = b1 * inv;
    atomicAdd(&g_cnt[i0], 1);
    atomicAdd(&g_cnt[i1], 1);
}

// ---------------- 4: offsets ----------------------------------------------
__global__ void k_offsets() {
    if (threadIdx.x == 0 && blockIdx.x == 0) {
        int off = 0;
        for (int e = 0; e < N_EXP; e++) {
            g_seg[e] = off;
            off += ((g_cnt[e] + BM - 1) / BM) * BM;
        }
        g_seg[N_EXP] = off;
    }
}

// ---------------- 5: scatter -----------------------------------------------
__global__ void k_scatter() {
    int t = blockIdx.x * blockDim.x + threadIdx.x;
    if (t >= T_TOK) return;
    #pragma unroll
    for (int k = 0; k < 2; k++) {
        int e = g_topi[t * 2 + k];
        int pos = atomicAdd(&g_fill[e], 1);
        int idx = g_seg[e] + pos;
        g_ptok[idx] = t;
        g_pscale[idx] = g_topp[t * 2 + k];
        g_pslot[idx] = k;
    }
}

// ---------------- 6: gather + bf16 hi/lo split -----------------------------
__global__ void k_gather_split() {
    int p = blockIdx.x;
    int tok = g_ptok[p];
    int tid = threadIdx.x;
    float4 v = (tok >= 0) ? ((const float4*)(g_x + (size_t)tok * H_DIM))[tid]
                          : make_float4(0.f, 0.f, 0.f, 0.f);
    __nv_bfloat16 h0 = __float2bfloat16(v.x), h1 = __float2bfloat16(v.y);
    __nv_bfloat16 h2 = __float2bfloat16(v.z), h3 = __float2bfloat16(v.w);
    __nv_bfloat16 l0 = __float2bfloat16(v.x - __bfloat162float(h0));
    __nv_bfloat16 l1 = __float2bfloat16(v.y - __bfloat162float(h1));
    __nv_bfloat16 l2 = __float2bfloat16(v.z - __bfloat162float(h2));
    __nv_bfloat16 l3 = __float2bfloat16(v.w - __bfloat162float(h3));
    uint2 ph = make_uint2(pack2(h0, h1), pack2(h2, h3));
    uint2 pl = make_uint2(pack2(l0, l1), pack2(l2, l3));
    ((uint2*)(g_xg_hi + (size_t)p * H_DIM))[tid] = ph;
    ((uint2*)(g_xg_lo + (size_t)p * H_DIM))[tid] = pl;
}

// ======================= GEMM1: gate+up, HMMA split ========================
// Block: 128 rows x 64 f-cols (gate AND up). 8 warps = 4(M) x 2(N).
// Stage rows: Ah[0,128) Al[128,256) Gh[256,320) Gl[320,384) Uh[384,448) Ul[448,512)
#define NST1 (H_DIM / 32)   // 32
__global__ __launch_bounds__(256)
void k_gemm1_m() {
    int e = blockIdx.x / MAX_TILES;
    int tile = blockIdx.x % MAX_TILES;
    int row0 = tile * BM;
    if (row0 >= g_cnt[e]) return;
    int seg = g_seg[e];
    int nblk = blockIdx.y * 64;
    int tid = threadIdx.x;

    extern __shared__ __align__(16) char smch[];
    __shared__ float sScale[128];
    uint32_t smb = smem_u32(smch);
    if (tid < 128) sScale[tid] = g_pscale[seg + row0 + tid];

    const __nv_bfloat16* pah = g_xg_hi + (size_t)(seg + row0) * H_DIM;
    const __nv_bfloat16* pal = g_xg_lo + (size_t)(seg + row0) * H_DIM;
    const __nv_bfloat16* pgh = g_wgt_hi + ((size_t)e * F_DIM + nblk) * H_DIM;
    const __nv_bfloat16* pgl = g_wgt_lo + ((size_t)e * F_DIM + nblk) * H_DIM;
    const __nv_bfloat16* puh = g_wut_hi + ((size_t)e * F_DIM + nblk) * H_DIM;
    const __nv_bfloat16* pul = g_wut_lo + ((size_t)e * F_DIM + nblk) * H_DIM;

    int ctid = tid, cr = ctid >> 2, cc = (ctid & 3) * 16;

    // ---- stage loader (8 chunks of 16B per thread) ----
    #define LOAD1(s)  do {                                                        \
        int kk_ = (s) * 32;                                                       \
        uint32_t b_ = smb + ((s) % NSTAGE) * STAGE_BYTES;                         \
        _Pragma("unroll")                                                         \
        for (int i_ = 0; i_ < 8; i_++) {                                          \
            int row_ = cr + i_ * 64;                                              \
            const __nv_bfloat16* src_;                                            \
            if (row_ < 128)      src_ = pah + (size_t)row_ * H_DIM;               \
            else if (row_ < 256) src_ = pal + (size_t)(row_-128) * H_DIM;         \
            else if (row_ < 320) src_ = pgh + (size_t)(row_-256) * H_DIM;         \
            else if (row_ < 384) src_ = pgl + (size_t)(row_-320) * H_DIM;         \
            else if (row_ < 448) src_ = puh + (size_t)(row_-384) * H_DIM;         \
            else                 src_ = pul + (size_t)(row_-448) * H_DIM;         \
            cp16(b_ + row_ * SM_PITCH + cc, src_ + kk_ + cc / 2);                 \
        }                                                                         \
        cp_commit();                                                              \
    } while (0)

    LOAD1(0); LOAD1(1); LOAD1(2);

    int lane = tid & 31, warp = tid >> 5;
    int wm = warp >> 1, wn = warp & 1;
    int gr = lane >> 2, cp4 = (lane & 3) * 4;
    int m0 = wm * 32, n0 = wn * 32;

    float accg[2][4][4], accu[2][4][4];
    #pragma unroll
    for (int i = 0; i < 2; i++)
        #pragma unroll
        for (int j = 0; j < 4; j++)
            #pragma unroll
            for (int k = 0; k < 4; k++) { accg[i][j][k] = 0.f; accu[i][j][k] = 0.f; }

    for (int s = 0; s < NST1; s++) {
        cp_wait2();
        __syncthreads();
        uint32_t b = smb + (s % NSTAGE) * STAGE_BYTES;
        #pragma unroll
        for (int kh = 0; kh < 2; kh++) {
            uint32_t ko = kh * 32;
            uint32_t ah[2][4], al[2][4];
            #pragma unroll
            for (int mi = 0; mi < 2; mi++) {
                uint32_t ra = b + (uint32_t)(m0 + mi * 16 + gr) * SM_PITCH + ko + cp4;
                ah[mi][0] = lds32(ra);
                ah[mi][1] = lds32(ra + 8 * SM_PITCH);
                ah[mi][2] = lds32(ra + 16);
                ah[mi][3] = lds32(ra + 8 * SM_PITCH + 16);
                uint32_t rl = ra + 128 * SM_PITCH;
                al[mi][0] = lds32(rl);
                al[mi][1] = lds32(rl + 8 * SM_PITCH);
                al[mi][2] = lds32(rl + 16);
                al[mi][3] = lds32(rl + 8 * SM_PITCH + 16);
            }
            #pragma unroll
            for (int ni = 0; ni < 4; ni++) {
                uint32_t rg = b + (uint32_t)(256 + n0 + ni * 8 + gr) * SM_PITCH + ko + cp4;
                uint32_t gh0 = lds32(rg),                 gh1 = lds32(rg + 16);
                uint32_t gl0 = lds32(rg + 64 * SM_PITCH), gl1 = lds32(rg + 64 * SM_PITCH + 16);
                uint32_t ru = rg + 128 * SM_PITCH;
                uint32_t uh0 = lds32(ru),                 uh1 = lds32(ru + 16);
                uint32_t ul0 = lds32(ru + 64 * SM_PITCH), ul1 = lds32(ru + 64 * SM_PITCH + 16);
                #pragma unroll
                for (int mi = 0; mi < 2; mi++) {
                    mma16816(accg[mi][ni], ah[mi], gh0, gh1);
                    mma16816(accg[mi][ni], ah[mi], gl0, gl1);
                    mma16816(accg[mi][ni], al[mi], gh0, gh1);
                    mma16816(accu[mi][ni], ah[mi], uh0, uh1);
                    mma16816(accu[mi][ni], ah[mi], ul0, ul1);
                    mma16816(accu[mi][ni], al[mi], uh0, uh1);
                }
            }
        }
        __syncthreads();
        if (s + NSTAGE < NST1) LOAD1(s + NSTAGE);
    }

    // epilogue: h = scale * silu(gate) * up -> split bf16
    #pragma unroll
    for (int mi = 0; mi < 2; mi++) {
        int mA = m0 + mi * 16 + gr;
        float scA = sScale[mA];
        float scB = sScale[mA + 8];
        #pragma unroll
        for (int ni = 0; ni < 4; ni++) {
            int fcol = nblk + n0 + ni * 8 + (lane & 3) * 2;
            #pragma unroll
            for (int half = 0; half < 2; half++) {
                float g0 = accg[mi][ni][half * 2], g1 = accg[mi][ni][half * 2 + 1];
                float u0 = accu[mi][ni][half * 2], u1 = accu[mi][ni][half * 2 + 1];
                float sc = half ? scB : scA;
                int m = mA + half * 8;
                float h0 = sc * (g0 / (1.f + __expf(-g0))) * u0;
                float h1 = sc * (g1 / (1.f + __expf(-g1))) * u1;
                __nv_bfloat16 a0 = __float2bfloat16(h0), a1 = __float2bfloat16(h1);
                __nv_bfloat16 b0 = __float2bfloat16(h0 - __bfloat162float(a0));
                __nv_bfloat16 b1 = __float2bfloat16(h1 - __bfloat162float(a1));
                size_t off = (size_t)(seg + row0 + m) * F_DIM + fcol;
                *(uint32_t*)(g_h_hi + off) = pack2(a0, a1);
                *(uint32_t*)(g_h_lo + off) = pack2(b0, b1);
            }
        }
    }
    #undef LOAD1
}

// ======================= GEMM2: down proj, HMMA split ======================
// Block: 128 rows x 128 h-cols. 8 warps = 4(M) x 2(N), warp N-tile 64.
// Stage rows: Ah[0,128) Al[128,256) Bh[256,384) Bl[384,512)
#define NST2 (F_DIM / 32)   // 88
__global__ __launch_bounds__(256)
void k_gemm2_m() {
    int e = blockIdx.x / MAX_TILES;
    int tile = blockIdx.x % MAX_TILES;
    int row0 = tile * BM;
    if (row0 >= g_cnt[e]) return;
    int seg = g_seg[e];
    int nblk = blockIdx.y * 128;
    int tid = threadIdx.x;

    extern __shared__ __align__(16) char smch[];
    __shared__ int sTok[128];
    __shared__ int sSlot[128];
    uint32_t smb = smem_u32(smch);
    if (tid < 128) {
        sTok[tid]  = g_ptok[seg + row0 + tid];
        sSlot[tid] = g_pslot[seg + row0 + tid];
    }

    const __nv_bfloat16* pah = g_h_hi + (size_t)(seg + row0) * F_DIM;
    const __nv_bfloat16* pal = g_h_lo + (size_t)(seg + row0) * F_DIM;
    const __nv_bfloat16* pbh = g_wdt_hi + ((size_t)e * H_DIM + nblk) * F_DIM;
    const __nv_bfloat16* pbl = g_wdt_lo + ((size_t)e * H_DIM + nblk) * F_DIM;

    int cr = tid >> 2, cc = (tid & 3) * 16;

    #define LOAD2(s)  do {                                                        \
        int kk_ = (s) * 32;                                                       \
        uint32_t b_ = smb + ((s) % NSTAGE) * STAGE_BYTES;                         \
        _Pragma("unroll")                                                         \
        for (int i_ = 0; i_ < 8; i_++) {                                          \
            int row_ = cr + i_ * 64;                                              \
            const __nv_bfloat16* src_;                                            \
            if (row_ < 128)      src_ = pah + (size_t)row_ * F_DIM;               \
            else if (row_ < 256) src_ = pal + (size_t)(row_-128) * F_DIM;         \
            else if (row_ < 384) src_ = pbh + (size_t)(row_-256) * F_DIM;         \
            else                 src_ = pbl + (size_t)(row_-384) * F_DIM;         \
            cp16(b_ + row_ * SM_PITCH + cc, src_ + kk_ + cc / 2);                 \
        }                                                                         \
        cp_commit();                                                              \
    } while (0)

    LOAD2(0); LOAD2(1); LOAD2(2);

    int lane = tid & 31, warp = tid >> 5;
    int wm = warp >> 1, wn = warp & 1;
    int gr = lane >> 2, cp4 = (lane & 3) * 4;
    int m0 = wm * 32, n0 = wn * 64;

    float acc[2][8][4];
    #pragma unroll
    for (int i = 0; i < 2; i++)
        #pragma unroll
        for (int j = 0; j < 8; j++)
            #pragma unroll
            for (int k = 0; k < 4; k++) acc[i][j][k] = 0.f;

    for (int s = 0; s < NST2; s++) {
        cp_wait2();
        __syncthreads();
        uint32_t b = smb + (s % NSTAGE) * STAGE_BYTES;
        #pragma unroll
        for (int kh = 0; kh < 2; kh++) {
            uint32_t ko = kh * 32;
            uint32_t ah[2][4], al[2][4];
            #pragma unroll
            for (int mi = 0; mi < 2; mi++) {
                uint32_t ra = b + (uint32_t)(m0 + mi * 16 + gr) * SM_PITCH + ko + cp4;
                ah[mi][0] = lds32(ra);
                ah[mi][1] = lds32(ra + 8 * SM_PITCH);
                ah[mi][2] = lds32(ra + 16);
                ah[mi][3] = lds32(ra + 8 * SM_PITCH + 16);
                uint32_t rl = ra + 128 * SM_PITCH;
                al[mi][0] = lds32(rl);
                al[mi][1] = lds32(rl + 8 * SM_PITCH);
                al[mi][2] = lds32(rl + 16);
                al[mi][3] = lds32(rl + 8 * SM_PITCH + 16);
            }
            #pragma unroll
            for (int ni = 0; ni < 8; ni++) {
                uint32_t rb = b + (uint32_t)(256 + n0 + ni * 8 + gr) * SM_PITCH + ko + cp4;
                uint32_t bh0 = lds32(rb),                  bh1 = lds32(rb + 16);
                uint32_t bl0 = lds32(rb + 128 * SM_PITCH), bl1 = lds32(rb + 128 * SM_PITCH + 16);
                #pragma unroll
                for (int mi = 0; mi < 2; mi++) {
                    mma16816(acc[mi][ni], ah[mi], bh0, bh1);
                    mma16816(acc[mi][ni], ah[mi], bl0, bl1);
                    mma16816(acc[mi][ni], al[mi], bh0, bh1);
                }
            }
        }
        __syncthreads();
        if (s + NSTAGE < NST2) LOAD2(s + NSTAGE);
    }

    // epilogue -> per-slot partial buffers
    #pragma unroll
    for (int mi = 0; mi < 2; mi++) {
        int mA = m0 + mi * 16 + gr;
        #pragma unroll
        for (int half = 0; half < 2; half++) {
            int m = mA + half * 8;
            int tok = sTok[m], slot = sSlot[m];
            if (tok < 0) continue;
            float* dst = g_part[slot] + (size_t)tok * H_DIM;
            #pragma unroll
            for (int ni = 0; ni < 8; ni++) {
                int col = nblk + n0 + ni * 8 + (lane & 3) * 2;
                float2 v = make_float2(acc[mi][ni][half * 2], acc[mi][ni][half * 2 + 1]);
                *(float2*)(dst + col) = v;
            }
        }
    }
    #undef LOAD2
}

// ---------------- 9: sum slot partials -------------------------------------
__global__ void k_final(float* __restrict__ out) {
    int i = blockIdx.x * blockDim.x + threadIdx.x;
    float4 a = ((const float4*)g_part[0])[i];
    float4 b = ((const float4*)g_part[1])[i];
    float4 o;
    o.x = a.x + b.x; o.y = a.y + b.y; o.z = a.z + b.z; o.w = a.w + b.w;
    ((float4*)out)[i] = o;
}

// ---------------- launcher -------------------------------------------------
extern "C" void kernel_launch(void* const* d_in, const int* in_sizes, int n_in,
                              void* d_out, int out_size) {
    const float* hs  = (const float*)d_in[0];
    const float* lnw = (const float*)d_in[1];
    const float* rw  = (const float*)d_in[2];
    const float* wg  = (const float*)d_in[3];
    const float* wu  = (const float*)d_in[4];
    const float* wd  = (const float*)d_in[5];
    float* out = (float*)d_out;

    cudaFuncSetAttribute(k_gemm1_m, cudaFuncAttributeMaxDynamicSharedMemorySize, GEMM_SMEM);
    cudaFuncSetAttribute(k_gemm2_m, cudaFuncAttributeMaxDynamicSharedMemorySize, GEMM_SMEM);

    k_init<<<(CAP + 255) / 256, 256>>>();
    k_rmsnorm<<<T_TOK, 256>>>(hs, lnw);
    k_transpose_split<<<dim3(F_DIM / 32, H_DIM / 32, N_EXP), dim3(32, 8)>>>(wg, 0, H_DIM, F_DIM);
    k_transpose_split<<<dim3(F_DIM / 32, H_DIM / 32, N_EXP), dim3(32, 8)>>>(wu, 1, H_DIM, F_DIM);
    k_transpose_split<<<dim3(H_DIM / 32, F_DIM / 32, N_EXP), dim3(32, 8)>>>(wd, 2, F_DIM, H_DIM);
    k_router<<<T_TOK / 256, 256>>>(rw);
    k_offsets<<<1, 32>>>();
    k_scatter<<<T_TOK / 256, 256>>>();
    k_gather_split<<<CAP, 256>>>();
    k_gemm1_m<<<dim3(N_EXP * MAX_TILES, F_DIM / 64), 256, GEMM_SMEM>>>();
    k_gemm2_m<<<dim3(N_EXP * MAX_TILES, H_DIM / 128), 256, GEMM_SMEM>>>();
    k_final<<<(T_TOK * H_DIM / 4) / 256, 256>>>(out);
}

// round 11
// speedup vs baseline: 1.8665x; 1.0955x over previous
#include <cuda_runtime.h>
#include <cuda_bf16.h>
#include <cstdint>

#define T_TOK 4096
#define H_DIM 1024
#define F_DIM 2816
#define N_EXP 8
#define BM 128
#define MAX_TILES 32
#define CAP 9216

#define SM_PITCH 80                 // bytes per 32-bf16 smem row (20 banks -> conflict-free)
#define STAGE_ROWS 512
#define STAGE_BYTES (STAGE_ROWS * SM_PITCH)   // 40960
#define NSTAGE 3
#define GEMM_SMEM (NSTAGE * STAGE_BYTES)      // 122880

// ---------------- scratch (device globals) --------------------------------
__device__ float          g_x[(size_t)T_TOK * H_DIM];
__device__ __nv_bfloat16  g_xg_hi[(size_t)CAP * H_DIM];
__device__ __nv_bfloat16  g_xg_lo[(size_t)CAP * H_DIM];
__device__ __nv_bfloat16  g_h_hi[(size_t)CAP * F_DIM];
__device__ __nv_bfloat16  g_h_lo[(size_t)CAP * F_DIM];
__device__ __nv_bfloat16  g_wgt_hi[(size_t)N_EXP * F_DIM * H_DIM];  // [e][f][h]
__device__ __nv_bfloat16  g_wgt_lo[(size_t)N_EXP * F_DIM * H_DIM];
__device__ __nv_bfloat16  g_wut_hi[(size_t)N_EXP * F_DIM * H_DIM];
__device__ __nv_bfloat16  g_wut_lo[(size_t)N_EXP * F_DIM * H_DIM];
__device__ __nv_bfloat16  g_wdt_hi[(size_t)N_EXP * H_DIM * F_DIM]; // [e][h][f]
__device__ __nv_bfloat16  g_wdt_lo[(size_t)N_EXP * H_DIM * F_DIM];
__device__ float          g_part[2][(size_t)T_TOK * H_DIM];
__device__ int   g_cnt[N_EXP];
__device__ int   g_fill[N_EXP];
__device__ int   g_seg[N_EXP + 1];
__device__ int   g_ptok[CAP];
__device__ float g_pscale[CAP];
__device__ int   g_pslot[CAP];
__device__ int   g_topi[T_TOK * 2];
__device__ float g_topp[T_TOK * 2];

// ---------------- helpers --------------------------------------------------
__device__ __forceinline__ uint32_t smem_u32(const void* p) {
    uint32_t a;
    asm("{ .reg .u64 t; cvta.to.shared.u64 t, %1; cvt.u32.u64 %0, t; }" : "=r"(a) : "l"(p));
    return a;
}
__device__ __forceinline__ void cp16(uint32_t dst, const void* src) {
    asm volatile("cp.async.cg.shared.global [%0], [%1], 16;" :: "r"(dst), "l"(src));
}
__device__ __forceinline__ void cp_commit() {
    asm volatile("cp.async.commit_group;" ::: "memory");
}
__device__ __forceinline__ void cp_wait2() {
    asm volatile("cp.async.wait_group 2;" ::: "memory");
}
__device__ __forceinline__ void ldsm4(uint32_t* r, uint32_t a) {
    asm volatile("ldmatrix.sync.aligned.m8n8.x4.shared.b16 {%0,%1,%2,%3}, [%4];"
                 : "=r"(r[0]), "=r"(r[1]), "=r"(r[2]), "=r"(r[3]) : "r"(a));
}
__device__ __forceinline__ void mma16816(float* c, const uint32_t* a, uint32_t b0, uint32_t b1) {
    asm volatile(
        "mma.sync.aligned.m16n8k16.row.col.f32.bf16.bf16.f32 "
        "{%0,%1,%2,%3}, {%4,%5,%6,%7}, {%8,%9}, {%0,%1,%2,%3};"
        : "+f"(c[0]), "+f"(c[1]), "+f"(c[2]), "+f"(c[3])
        : "r"(a[0]), "r"(a[1]), "r"(a[2]), "r"(a[3]), "r"(b0), "r"(b1));
}
__device__ __forceinline__ uint32_t pack2(__nv_bfloat16 a, __nv_bfloat16 b) {
    return (uint32_t)__bfloat16_as_ushort(a) | ((uint32_t)__bfloat16_as_ushort(b) << 16);
}

// ---------------- 0: init --------------------------------------------------
__global__ void k_init() {
    int i = blockIdx.x * blockDim.x + threadIdx.x;
    if (i < N_EXP) { g_cnt[i] = 0; g_fill[i] = 0; }
    if (i < CAP) { g_ptok[i] = -1; g_pscale[i] = 0.f; }
}

// ---------------- 1: RMSNorm ----------------------------------------------
__global__ void k_rmsnorm(const float* __restrict__ hs, const float* __restrict__ lnw) {
    int t = blockIdx.x;
    const float4* row = (const float4*)(hs + (size_t)t * H_DIM);
    __shared__ float red[256];
    float4 v = row[threadIdx.x];
    float s = v.x * v.x + v.y * v.y + v.z * v.z + v.w * v.w;
    red[threadIdx.x] = s;
    __syncthreads();
    for (int off = 128; off > 0; off >>= 1) {
        if (threadIdx.x < off) red[threadIdx.x] += red[threadIdx.x + off];
        __syncthreads();
    }
    float rs = rsqrtf(red[0] * (1.0f / H_DIM) + 1e-5f);
    float4 w = ((const float4*)lnw)[threadIdx.x];
    float4 o;
    o.x = v.x * rs * w.x; o.y = v.y * rs * w.y;
    o.z = v.z * rs * w.z; o.w = v.w * rs * w.w;
    ((float4*)(g_x + (size_t)t * H_DIM))[threadIdx.x] = o;
}

// ---------------- 2: weight transpose + bf16 hi/lo split ------------------
__global__ void k_transpose_split(const float* __restrict__ src, int which, int R, int C) {
    __shared__ float t[32][33];
    size_t eoff = (size_t)blockIdx.z * (size_t)R * C;
    int c0 = blockIdx.x * 32, r0 = blockIdx.y * 32;
    const float* s = src + eoff;
    #pragma unroll
    for (int i = threadIdx.y; i < 32; i += 8)
        t[i][threadIdx.x] = s[(size_t)(r0 + i) * C + c0 + threadIdx.x];
    __syncthreads();
    __nv_bfloat16 *dhi, *dlo;
    if (which == 0)      { dhi = g_wgt_hi; dlo = g_wgt_lo; }
    else if (which == 1) { dhi = g_wut_hi; dlo = g_wut_lo; }
    else                 { dhi = g_wdt_hi; dlo = g_wdt_lo; }
    dhi += eoff; dlo += eoff;
    #pragma unroll
    for (int i = threadIdx.y; i < 32; i += 8) {
        int ro = c0 + i;
        int co = r0 + threadIdx.x;
        float v = t[threadIdx.x][i];
        __nv_bfloat16 h = __float2bfloat16(v);
        __nv_bfloat16 l = __float2bfloat16(v - __bfloat162float(h));
        dhi[(size_t)ro * R + co] = h;
        dlo[(size_t)ro * R + co] = l;
    }
}

// ---------------- 3: router (warp per token, coalesced) -------------------
__global__ void k_router(const float* __restrict__ rw) {
    int wid = threadIdx.x >> 5, lane = threadIdx.x & 31;
    int t = blockIdx.x * 8 + wid;
    const float4* xr = (const float4*)(g_x + (size_t)t * H_DIM);
    float acc[8] = {0, 0, 0, 0, 0, 0, 0, 0};
    #pragma unroll
    for (int it = 0; it < 8; it++) {
        int k4 = it * 32 + lane;             // float4 index (256 per row)
        float4 xv = xr[k4];
        const float4* rp = (const float4*)(rw + (size_t)k4 * 32);  // 4 k-rows x 8
        float4 r0 = rp[0], r1 = rp[1];
        float4 r2 = rp[2], r3 = rp[3];
        float4 r4 = rp[4], r5 = rp[5];
        float4 r6 = rp[6], r7 = rp[7];
        acc[0] += xv.x * r0.x + xv.y * r2.x + xv.z * r4.x + xv.w * r6.x;
        acc[1] += xv.x * r0.y + xv.y * r2.y + xv.z * r4.y + xv.w * r6.y;
        acc[2] += xv.x * r0.z + xv.y * r2.z + xv.z * r4.z + xv.w * r6.z;
        acc[3] += xv.x * r0.w + xv.y * r2.w + xv.z * r4.w + xv.w * r6.w;
        acc[4] += xv.x * r1.x + xv.y * r3.x + xv.z * r5.x + xv.w * r7.x;
        acc[5] += xv.x * r1.y + xv.y * r3.y + xv.z * r5.y + xv.w * r7.y;
        acc[6] += xv.x * r1.z + xv.y * r3.z + xv.z * r5.z + xv.w * r7.z;
        acc[7] += xv.x * r1.w + xv.y * r3.w + xv.z * r5.w + xv.w * r7.w;
    }
    #pragma unroll
    for (int off = 16; off > 0; off >>= 1)
        #pragma unroll
        for (int e = 0; e < 8; e++)
            acc[e] += __shfl_xor_sync(0xffffffffu, acc[e], off);
    if (lane == 0) {
        float m = acc[0];
        #pragma unroll
        for (int e = 1; e < 8; e++) m = fmaxf(m, acc[e]);
        float p[8]; float s = 0.f;
        #pragma unroll
        for (int e = 0; e < 8; e++) { p[e] = expf(acc[e] - m); s += p[e]; }
        float inv = 1.f / s;
        int i0 = 0; float b0 = p[0];
        #pragma unroll
        for (int e = 1; e < 8; e++) if (p[e] > b0) { b0 = p[e]; i0 = e; }
        int i1 = -1; float b1 = -1.f;
        #pragma unroll
        for (int e = 0; e < 8; e++) if (e != i0 && p[e] > b1) { b1 = p[e]; i1 = e; }
        g_topi[t * 2] = i0;       g_topi[t * 2 + 1] = i1;
        g_topp[t * 2] = b0 * inv; g_topp[t * 2 + 1] = b1 * inv;
        atomicAdd(&g_cnt[i0], 1);
        atomicAdd(&g_cnt[i1], 1);
    }
}

// ---------------- 4: offsets ----------------------------------------------
__global__ void k_offsets() {
    if (threadIdx.x == 0 && blockIdx.x == 0) {
        int off = 0;
        for (int e = 0; e < N_EXP; e++) {
            g_seg[e] = off;
            off += ((g_cnt[e] + BM - 1) / BM) * BM;
        }
        g_seg[N_EXP] = off;
    }
}

// ---------------- 5: scatter -----------------------------------------------
__global__ void k_scatter() {
    int t = blockIdx.x * blockDim.x + threadIdx.x;
    if (t >= T_TOK) return;
    #pragma unroll
    for (int k = 0; k < 2; k++) {
        int e = g_topi[t * 2 + k];
        int pos = atomicAdd(&g_fill[e], 1);
        int idx = g_seg[e] + pos;
        g_ptok[idx] = t;
        g_pscale[idx] = g_topp[t * 2 + k];
        g_pslot[idx] = k;
    }
}

// ---------------- 6: gather + bf16 hi/lo split -----------------------------
__global__ void k_gather_split() {
    int p = blockIdx.x;
    int tok = g_ptok[p];
    int tid = threadIdx.x;
    float4 v = (tok >= 0) ? ((const float4*)(g_x + (size_t)tok * H_DIM))[tid]
                          : make_float4(0.f, 0.f, 0.f, 0.f);
    __nv_bfloat16 h0 = __float2bfloat16(v.x), h1 = __float2bfloat16(v.y);
    __nv_bfloat16 h2 = __float2bfloat16(v.z), h3 = __float2bfloat16(v.w);
    __nv_bfloat16 l0 = __float2bfloat16(v.x - __bfloat162float(h0));
    __nv_bfloat16 l1 = __float2bfloat16(v.y - __bfloat162float(h1));
    __nv_bfloat16 l2 = __float2bfloat16(v.z - __bfloat162float(h2));
    __nv_bfloat16 l3 = __float2bfloat16(v.w - __bfloat162float(h3));
    ((uint2*)(g_xg_hi + (size_t)p * H_DIM))[tid] = make_uint2(pack2(h0, h1), pack2(h2, h3));
    ((uint2*)(g_xg_lo + (size_t)p * H_DIM))[tid] = make_uint2(pack2(l0, l1), pack2(l2, l3));
}

// ======================= GEMM1: gate+up, HMMA split ========================
// Block: 128 rows x 64 f-cols (gate AND up). 8 warps = 4(M) x 2(N).
// Stage rows: Ah[0,128) Al[128,256) Gh[256,320) Gl[320,384) Uh[384,448) Ul[448,512)
#define NST1 (H_DIM / 32)   // 32
__global__ __launch_bounds__(256)
void k_gemm1_m() {
    int e = blockIdx.x / MAX_TILES;
    int tile = blockIdx.x % MAX_TILES;
    int row0 = tile * BM;
    if (row0 >= g_cnt[e]) return;
    int seg = g_seg[e];
    int nblk = blockIdx.y * 64;
    int tid = threadIdx.x;

    extern __shared__ __align__(16) char smch[];
    __shared__ float sScale[128];
    uint32_t smb = smem_u32(smch);
    if (tid < 128) sScale[tid] = g_pscale[seg + row0 + tid];

    const __nv_bfloat16* pah = g_xg_hi + (size_t)(seg + row0) * H_DIM;
    const __nv_bfloat16* pal = g_xg_lo + (size_t)(seg + row0) * H_DIM;
    const __nv_bfloat16* pgh = g_wgt_hi + ((size_t)e * F_DIM + nblk) * H_DIM;
    const __nv_bfloat16* pgl = g_wgt_lo + ((size_t)e * F_DIM + nblk) * H_DIM;
    const __nv_bfloat16* puh = g_wut_hi + ((size_t)e * F_DIM + nblk) * H_DIM;
    const __nv_bfloat16* pul = g_wut_lo + ((size_t)e * F_DIM + nblk) * H_DIM;

    int cr = tid >> 2, cc = (tid & 3) * 16;

    #define LOAD1(s)  do {                                                        \
        int kk_ = (s) * 32;                                                       \
        uint32_t b_ = smb + ((s) % NSTAGE) * STAGE_BYTES;                         \
        _Pragma("unroll")                                                         \
        for (int i_ = 0; i_ < 8; i_++) {                                          \
            int row_ = cr + i_ * 64;                                              \
            const __nv_bfloat16* src_;                                            \
            if (row_ < 128)      src_ = pah + (size_t)row_ * H_DIM;               \
            else if (row_ < 256) src_ = pal + (size_t)(row_-128) * H_DIM;         \
            else if (row_ < 320) src_ = pgh + (size_t)(row_-256) * H_DIM;         \
            else if (row_ < 384) src_ = pgl + (size_t)(row_-320) * H_DIM;         \
            else if (row_ < 448) src_ = puh + (size_t)(row_-384) * H_DIM;         \
            else                 src_ = pul + (size_t)(row_-448) * H_DIM;         \
            cp16(b_ + row_ * SM_PITCH + cc, src_ + kk_ + cc / 2);                 \
        }                                                                         \
        cp_commit();                                                              \
    } while (0)

    LOAD1(0); LOAD1(1); LOAD1(2);

    int lane = tid & 31, warp = tid >> 5;
    int wm = warp >> 1, wn = warp & 1;
    int gr = lane >> 2;
    int m0 = wm * 32, n0 = wn * 32;

    // ldmatrix lane addressing (non-trans, R6 [row][k] pitch-80 layout)
    uint32_t aRowOff = (uint32_t)(m0 + (lane & 15)) * SM_PITCH + (lane >> 4) * 16;
    uint32_t bRowOff = (uint32_t)(256 + n0 + ((lane >> 4) << 3) + (lane & 7)) * SM_PITCH
                     + ((lane >> 3) & 1) * 16;

    float accg[2][4][4], accu[2][4][4];
    #pragma unroll
    for (int i = 0; i < 2; i++)
        #pragma unroll
        for (int j = 0; j < 4; j++)
            #pragma unroll
            for (int k = 0; k < 4; k++) { accg[i][j][k] = 0.f; accu[i][j][k] = 0.f; }

    for (int s = 0; s < NST1; s++) {
        cp_wait2();
        __syncthreads();
        uint32_t b = smb + (s % NSTAGE) * STAGE_BYTES;
        #pragma unroll
        for (int kh = 0; kh < 2; kh++) {
            uint32_t ko = kh * 32;
            uint32_t ah[2][4], al[2][4];
            ldsm4(ah[0], b + aRowOff + ko);
            ldsm4(ah[1], b + aRowOff + 16 * SM_PITCH + ko);
            ldsm4(al[0], b + aRowOff + 128 * SM_PITCH + ko);
            ldsm4(al[1], b + aRowOff + 144 * SM_PITCH + ko);
            #pragma unroll
            for (int q = 0; q < 2; q++) {
                uint32_t bq = b + bRowOff + (uint32_t)q * 16 * SM_PITCH + ko;
                uint32_t gh[4], gl[4], uh[4], ul[4];
                ldsm4(gh, bq);
                ldsm4(gl, bq + 64 * SM_PITCH);
                ldsm4(uh, bq + 128 * SM_PITCH);
                ldsm4(ul, bq + 192 * SM_PITCH);
                #pragma unroll
                for (int h2 = 0; h2 < 2; h2++) {
                    int ng = q * 2 + h2;
                    #pragma unroll
                    for (int mi = 0; mi < 2; mi++) {
                        mma16816(accg[mi][ng], ah[mi], gh[h2 * 2], gh[h2 * 2 + 1]);
                        mma16816(accg[mi][ng], ah[mi], gl[h2 * 2], gl[h2 * 2 + 1]);
                        mma16816(accg[mi][ng], al[mi], gh[h2 * 2], gh[h2 * 2 + 1]);
                        mma16816(accu[mi][ng], ah[mi], uh[h2 * 2], uh[h2 * 2 + 1]);
                        mma16816(accu[mi][ng], ah[mi], ul[h2 * 2], ul[h2 * 2 + 1]);
                        mma16816(accu[mi][ng], al[mi], uh[h2 * 2], uh[h2 * 2 + 1]);
                    }
                }
            }
        }
        __syncthreads();
        if (s + NSTAGE < NST1) LOAD1(s + NSTAGE);
    }

    // epilogue: h = scale * silu(gate) * up -> split bf16 (R6-proven)
    #pragma unroll
    for (int mi = 0; mi < 2; mi++) {
        int mA = m0 + mi * 16 + gr;
        float scA = sScale[mA];
        float scB = sScale[mA + 8];
        #pragma unroll
        for (int ni = 0; ni < 4; ni++) {
            int fcol = nblk + n0 + ni * 8 + (lane & 3) * 2;
            #pragma unroll
            for (int half = 0; half < 2; half++) {
                float g0 = accg[mi][ni][half * 2], g1 = accg[mi][ni][half * 2 + 1];
                float u0 = accu[mi][ni][half * 2], u1 = accu[mi][ni][half * 2 + 1];
                float sc = half ? scB : scA;
                int m = mA + half * 8;
                float h0 = sc * (g0 / (1.f + __expf(-g0))) * u0;
                float h1 = sc * (g1 / (1.f + __expf(-g1))) * u1;
                __nv_bfloat16 a0 = __float2bfloat16(h0), a1 = __float2bfloat16(h1);
                __nv_bfloat16 b0 = __float2bfloat16(h0 - __bfloat162float(a0));
                __nv_bfloat16 b1 = __float2bfloat16(h1 - __bfloat162float(a1));
                size_t off = (size_t)(seg + row0 + m) * F_DIM + fcol;
                *(uint32_t*)(g_h_hi + off) = pack2(a0, a1);
                *(uint32_t*)(g_h_lo + off) = pack2(b0, b1);
            }
        }
    }
    #undef LOAD1
}

// ======================= GEMM2: down proj, HMMA split ======================
// Block: 128 rows x 128 h-cols. 8 warps = 4(M) x 2(N), warp N-tile 64.
// Stage rows: Ah[0,128) Al[128,256) Bh[256,384) Bl[384,512)
#define NST2 (F_DIM / 32)   // 88
__global__ __launch_bounds__(256)
void k_gemm2_m() {
    int e = blockIdx.x / MAX_TILES;
    int tile = blockIdx.x % MAX_TILES;
    int row0 = tile * BM;
    if (row0 >= g_cnt[e]) return;
    int seg = g_seg[e];
    int nblk = blockIdx.y * 128;
    int tid = threadIdx.x;

    extern __shared__ __align__(16) char smch[];
    __shared__ int sTok[128];
    __shared__ int sSlot[128];
    uint32_t smb = smem_u32(smch);
    if (tid < 128) {
        sTok[tid]  = g_ptok[seg + row0 + tid];
        sSlot[tid] = g_pslot[seg + row0 + tid];
    }

    const __nv_bfloat16* pah = g_h_hi + (size_t)(seg + row0) * F_DIM;
    const __nv_bfloat16* pal = g_h_lo + (size_t)(seg + row0) * F_DIM;
    const __nv_bfloat16* pbh = g_wdt_hi + ((size_t)e * H_DIM + nblk) * F_DIM;
    const __nv_bfloat16* pbl = g_wdt_lo + ((size_t)e * H_DIM + nblk) * F_DIM;

    int cr = tid >> 2, cc = (tid & 3) * 16;

    #define LOAD2(s)  do {                                                        \
        int kk_ = (s) * 32;                                                       \
        uint32_t b_ = smb + ((s) % NSTAGE) * STAGE_BYTES;                         \
        _Pragma("unroll")                                                         \
        for (int i_ = 0; i_ < 8; i_++) {                                          \
            int row_ = cr + i_ * 64;                                              \
            const __nv_bfloat16* src_;                                            \
            if (row_ < 128)      src_ = pah + (size_t)row_ * F_DIM;               \
            else if (row_ < 256) src_ = pal + (size_t)(row_-128) * F_DIM;         \
            else if (row_ < 384) src_ = pbh + (size_t)(row_-256) * F_DIM;         \
            else                 src_ = pbl + (size_t)(row_-384) * F_DIM;         \
            cp16(b_ + row_ * SM_PITCH + cc, src_ + kk_ + cc / 2);                 \
        }                                                                         \
        cp_commit();                                                              \
    } while (0)

    LOAD2(0); LOAD2(1); LOAD2(2);

    int lane = tid & 31, warp = tid >> 5;
    int wm = warp >> 1, wn = warp & 1;
    int gr = lane >> 2;
    int m0 = wm * 32, n0 = wn * 64;

    uint32_t aRowOff = (uint32_t)(m0 + (lane & 15)) * SM_PITCH + (lane >> 4) * 16;
    uint32_t bRowOff = (uint32_t)(256 + n0 + ((lane >> 4) << 3) + (lane & 7)) * SM_PITCH
                     + ((lane >> 3) & 1) * 16;

    float acc[2][8][4];
    #pragma unroll
    for (int i = 0; i < 2; i++)
        #pragma unroll
        for (int j = 0; j < 8; j++)
            #pragma unroll
            for (int k = 0; k < 4; k++) acc[i][j][k] = 0.f;

    for (int s = 0; s < NST2; s++) {
        cp_wait2();
        __syncthreads();
        uint32_t b = smb + (s % NSTAGE) * STAGE_BYTES;
        #pragma unroll
        for (int kh = 0; kh < 2; kh++) {
            uint32_t ko = kh * 32;
            uint32_t ah[2][4], al[2][4];
            ldsm4(ah[0], b + aRowOff + ko);
            ldsm4(ah[1], b + aRowOff + 16 * SM_PITCH + ko);
            ldsm4(al[0], b + aRowOff + 128 * SM_PITCH + ko);
            ldsm4(al[1], b + aRowOff + 144 * SM_PITCH + ko);
            #pragma unroll
            for (int q = 0; q < 4; q++) {
                uint32_t bq = b + bRowOff + (uint32_t)q * 16 * SM_PITCH + ko;
                uint32_t bh[4], bl[4];
                ldsm4(bh, bq);
                ldsm4(bl, bq + 128 * SM_PITCH);
                #pragma unroll
                for (int h2 = 0; h2 < 2; h2++) {
                    int ng = q * 2 + h2;
                    #pragma unroll
                    for (int mi = 0; mi < 2; mi++) {
                        mma16816(acc[mi][ng], ah[mi], bh[h2 * 2], bh[h2 * 2 + 1]);
                        mma16816(acc[mi][ng], ah[mi], bl[h2 * 2], bl[h2 * 2 + 1]);
                        mma16816(acc[mi][ng], al[mi], bh[h2 * 2], bh[h2 * 2 + 1]);
                    }
                }
            }
        }
        __syncthreads();
        if (s + NSTAGE < NST2) LOAD2(s + NSTAGE);
    }

    // epilogue -> per-slot partial buffers (R6-proven)
    #pragma unroll
    for (int mi = 0; mi < 2; mi++) {
        #pragma unroll
        for (int half = 0; half < 2; half++) {
            int m = m0 + mi * 16 + gr + half * 8;
            int tok = sTok[m], slot = sSlot[m];
            if (tok < 0) continue;
            float* dst = g_part[slot] + (size_t)tok * H_DIM;
            #pragma unroll
            for (int ng = 0; ng < 8; ng++) {
                int col = nblk + n0 + ng * 8 + (lane & 3) * 2;
                *(float2*)(dst + col) =
                    make_float2(acc[mi][ng][half * 2], acc[mi][ng][half * 2 + 1]);
            }
        }
    }
    #undef LOAD2
}

// ---------------- 9: sum slot partials -------------------------------------
__global__ void k_final(float* __restrict__ out) {
    int i = blockIdx.x * blockDim.x + threadIdx.x;
    float4 a = ((const float4*)g_part[0])[i];
    float4 b = ((const float4*)g_part[1])[i];
    float4 o;
    o.x = a.x + b.x; o.y = a.y + b.y; o.z = a.z + b.z; o.w = a.w + b.w;
    ((float4*)out)[i] = o;
}

// ---------------- launcher -------------------------------------------------
extern "C" void kernel_launch(void* const* d_in, const int* in_sizes, int n_in,
                              void* d_out, int out_size) {
    const float* hs  = (const float*)d_in[0];
    const float* lnw = (const float*)d_in[1];
    const float* rw  = (const float*)d_in[2];
    const float* wg  = (const float*)d_in[3];
    const float* wu  = (const float*)d_in[4];
    const float* wd  = (const float*)d_in[5];
    float* out = (float*)d_out;

    cudaFuncSetAttribute(k_gemm1_m, cudaFuncAttributeMaxDynamicSharedMemorySize, GEMM_SMEM);
    cudaFuncSetAttribute(k_gemm2_m, cudaFuncAttributeMaxDynamicSharedMemorySize, GEMM_SMEM);

    k_init<<<(CAP + 255) / 256, 256>>>();
    k_rmsnorm<<<T_TOK, 256>>>(hs, lnw);
    k_transpose_split<<<dim3(F_DIM / 32, H_DIM / 32, N_EXP), dim3(32, 8)>>>(wg, 0, H_DIM, F_DIM);
    k_transpose_split<<<dim3(F_DIM / 32, H_DIM / 32, N_EXP), dim3(32, 8)>>>(wu, 1, H_DIM, F_DIM);
    k_transpose_split<<<dim3(H_DIM / 32, F_DIM / 32, N_EXP), dim3(32, 8)>>>(wd, 2, F_DIM, H_DIM);
    k_router<<<T_TOK / 8, 256>>>(rw);
    k_offsets<<<1, 32>>>();
    k_scatter<<<T_TOK / 256, 256>>>();
    k_gather_split<<<CAP, 256>>>();
    k_gemm1_m<<<dim3(N_EXP * MAX_TILES, F_DIM / 64), 256, GEMM_SMEM>>>();
    k_gemm2_m<<<dim3(N_EXP * MAX_TILES, H_DIM / 128), 256, GEMM_SMEM>>>();
    k_final<<<(T_TOK * H_DIM / 4) / 256, 256>>>(out);
}